// round 3
// baseline (speedup 1.0000x reference)
#include <cuda_runtime.h>
#include <math.h>
#include <stdint.h>

#define DT 512
#define DB 256
#define DI 256
#define DH 256
#define DG 768
#define DP (DT * DB)

typedef unsigned long long u64;

// ---------------- device scratch ----------
__device__ int   g_src[DP];
__device__ int   g_order[DP];
__device__ int   g_len[DB];
__device__ int   g_maxlen;
__device__ int   g_ntrue;
__device__ float g_gi[(size_t)DP * DG];

// ---------------- f32x2 helpers ----------
__device__ __forceinline__ u64 pack2(float lo, float hi) {
    u64 r; asm("mov.b64 %0, {%1, %2};" : "=l"(r) : "f"(lo), "f"(hi)); return r;
}
__device__ __forceinline__ void unpack2(u64 v, float& lo, float& hi) {
    asm("mov.b64 {%0, %1}, %2;" : "=f"(lo), "=f"(hi) : "l"(v));
}
__device__ __forceinline__ void fma2(u64& d, u64 a, u64 b) {
    asm("fma.rn.f32x2 %0, %1, %2, %0;" : "+l"(d) : "l"(a), "l"(b));
}
__device__ __forceinline__ u64 add2(u64 a, u64 b) {
    u64 r; asm("add.rn.f32x2 %0, %1, %2;" : "=l"(r) : "l"(a), "l"(b)); return r;
}

// ---------------------------------------------------------------------------
// Kernel 1: lengths, packed mask, ranks, order[], src[]  (1 CTA, 1024 thr)
// ---------------------------------------------------------------------------
__global__ void k_prep(const int* __restrict__ mask) {
    __shared__ int sLen[DB];
    __shared__ int sWm[32], sWp[32];
    __shared__ int sMax;
    const int tid = threadIdx.x;
    if (tid < DB) sLen[tid] = 0;
    if (tid == 0) sMax = 0;
    __syncthreads();
    {
        const int b = tid & 255;
        int acc = 0;
        for (int t = tid >> 8; t < DT; t += 4) acc += (mask[(t << 8) + b] != 0) ? 1 : 0;
        atomicAdd(&sLen[b], acc);
    }
    __syncthreads();
    if (tid < DB) { g_len[tid] = sLen[tid]; atomicMax(&sMax, sLen[tid]); }
    __syncthreads();
    if (tid == 0) g_maxlen = sMax;

    const int base = tid << 7;
    int cm = 0, cp = 0;
    #pragma unroll 4
    for (int i = 0; i < 128; i++) {
        const int p = base + i;
        cm += (mask[p] != 0) ? 1 : 0;
        cp += ((p >> 8) < sLen[p & 255]) ? 1 : 0;
    }
    const int lane = tid & 31, wid = tid >> 5;
    int im = cm, ip = cp;
    #pragma unroll
    for (int d = 1; d < 32; d <<= 1) {
        const int um = __shfl_up_sync(0xffffffffu, im, d);
        const int up = __shfl_up_sync(0xffffffffu, ip, d);
        if (lane >= d) { im += um; ip += up; }
    }
    if (lane == 31) { sWm[wid] = im; sWp[wid] = ip; }
    __syncthreads();
    if (wid == 0) {
        const int am = sWm[lane], ap = sWp[lane];
        int jm = am, jp = ap;
        #pragma unroll
        for (int d = 1; d < 32; d <<= 1) {
            const int um = __shfl_up_sync(0xffffffffu, jm, d);
            const int up = __shfl_up_sync(0xffffffffu, jp, d);
            if (lane >= d) { jm += um; jp += up; }
        }
        sWm[lane] = jm - am;
        sWp[lane] = jp - ap;
        if (lane == 31) g_ntrue = jm;
    }
    __syncthreads();

    int mrank = sWm[wid] + im - cm;
    int prank = sWp[wid] + ip - cp;
    for (int i = 0; i < 128; i++) {
        const int p  = base + i;
        const int mt = (mask[p] != 0) ? 1 : 0;
        const int pt = ((p >> 8) < sLen[p & 255]) ? 1 : 0;
        if (mt) g_order[mrank] = p;
        g_src[p] = pt ? prank : -1;
        mrank += mt; prank += pt;
    }
    __syncthreads();
    for (int i = 0; i < 128; i++) {
        const int p = base + i;
        const int k = g_src[p];
        if (k >= 0) g_src[p] = g_order[k];
    }
}

// ---------------------------------------------------------------------------
// Kernel 2: gi = gather(x) @ W_ih^T + b_ih  (64x64x16 tile, f32x2)
// ---------------------------------------------------------------------------
__global__ void k_gi(const float* __restrict__ x,
                     const float* __restrict__ Wih,
                     const float* __restrict__ bih) {
    __shared__ float As[16][64];
    __shared__ float Bs[16][64];
    __shared__ int   sSrc[64];
    __shared__ int   sAny;
    const int tid = threadIdx.x;
    const int gt = blockIdx.x;
    const int pt = blockIdx.y;

    if (tid == 0) sAny = 0;
    __syncthreads();
    if (tid < 64) {
        const int s = g_src[(pt << 6) + tid];
        sSrc[tid] = (s >= 0) ? s : 0;
        if (s >= 0) sAny = 1;
    }
    __syncthreads();
    if (!sAny) return;

    u64 acc[4][2] = {{0ull, 0ull}, {0ull, 0ull}, {0ull, 0ull}, {0ull, 0ull}};
    const int tm = tid & 15, tn = tid >> 4;
    const int m  = tid >> 2;
    const int kk = (tid & 3) << 2;
    const float* xrow = x   + ((size_t)sSrc[m] << 8);
    const float* wrow = Wih + ((size_t)((gt << 6) + m) << 8);

    for (int k0 = 0; k0 < DI; k0 += 16) {
        const float4 av = *(const float4*)(xrow + k0 + kk);
        const float4 bv = *(const float4*)(wrow + k0 + kk);
        As[kk + 0][m] = av.x; As[kk + 1][m] = av.y; As[kk + 2][m] = av.z; As[kk + 3][m] = av.w;
        Bs[kk + 0][m] = bv.x; Bs[kk + 1][m] = bv.y; Bs[kk + 2][m] = bv.z; Bs[kk + 3][m] = bv.w;
        __syncthreads();
        #pragma unroll
        for (int k = 0; k < 16; k++) {
            const float4  a  = *(const float4*)&As[k][tm << 2];
            const double2 bd = *(const double2*)&Bs[k][tn << 2];
            const u64 b0 = __double_as_longlong(bd.x);
            const u64 b1 = __double_as_longlong(bd.y);
            const u64 a0 = pack2(a.x, a.x), a1 = pack2(a.y, a.y);
            const u64 a2 = pack2(a.z, a.z), a3 = pack2(a.w, a.w);
            fma2(acc[0][0], a0, b0); fma2(acc[0][1], a0, b1);
            fma2(acc[1][0], a1, b0); fma2(acc[1][1], a1, b1);
            fma2(acc[2][0], a2, b0); fma2(acc[2][1], a2, b1);
            fma2(acc[3][0], a3, b0); fma2(acc[3][1], a3, b1);
        }
        __syncthreads();
    }

    const float4 bias = *(const float4*)(bih + (gt << 6) + (tn << 2));
    const size_t gbase = (size_t)((pt << 6) + (tm << 2)) * DG + (gt << 6) + (tn << 2);
    #pragma unroll
    for (int i = 0; i < 4; i++) {
        float4 o;
        unpack2(acc[i][0], o.x, o.y);
        unpack2(acc[i][1], o.z, o.w);
        o.x += bias.x; o.y += bias.y; o.z += bias.z; o.w += bias.w;
        *(float4*)(g_gi + gbase + (size_t)i * DG) = o;
    }
}

// ---------------------------------------------------------------------------
// Kernel 3: persistent cluster recurrence, v2.
// 16 clusters x 8 CTAs x 512 threads. W slice resident + swizzled; h
// double-buffered + swizzled; ks-split k with bfly reduction.
// ---------------------------------------------------------------------------
#define CSZ 8
#define BPC 16
#define WKF 520                       // floats per (jp,gate) row
#define WOFF 0
#define WFLOATS (48 * WKF)            // 24960
#define HOFF0 WFLOATS                 // h buffers: 16 b x 256 floats, swizzled
#define HOFF1 (HOFF0 + BPC * 256)
#define SMEM_F (HOFF1 + BPC * 256)    // 33152 floats = 132608 B

// h element (b, k) lives at float offset b*256 + (u ^ ((u>>4)&3) ^ (b&7))*4 + (k&3), u=k>>2
__device__ __forceinline__ int h_off(int b, int k) {
    const int u = k >> 2;
    const int s = (u ^ ((u >> 4) & 3) ^ (b & 7));
    return (b << 8) + (s << 2) + (k & 3);
}

extern __shared__ float s_rec[];

__global__ void __cluster_dims__(CSZ, 1, 1) __launch_bounds__(512, 1)
k_rec(const float* __restrict__ Whh, const float* __restrict__ bhh,
      const float* __restrict__ hx, float* __restrict__ out, const size_t oe) {
    const int tid = threadIdx.x;
    uint32_t rank; asm("mov.u32 %0, %%cluster_ctarank;" : "=r"(rank));
    const int clu = blockIdx.x / CSZ;
    const int b0  = clu * BPC;

    uint32_t sbase;
    asm("{ .reg .u64 t; cvta.to.shared.u64 t, %1; cvt.u32.u64 %0, t; }"
        : "=r"(sbase) : "l"(s_rec));

    // --- resident W slice, swizzled: row (jp*3+g), unit u=k>>1 -> u^((u>>5)&3)
    for (int idx = tid; idx < 96 * 64; idx += 512) {
        const int row = idx >> 6;            // 0..95 = g*32 + jj
        const int g = row >> 5, jj = row & 31;
        const int kq = (idx & 63) << 2;
        const int jp = jj >> 1, jl = jj & 1;
        const float4 v = *(const float4*)(Whh +
            ((size_t)((g << 8) + ((int)rank << 5) + jj) << 8) + kq);
        float* rb = s_rec + WOFF + (jp * 3 + g) * WKF;
        #pragma unroll
        for (int e = 0; e < 4; e++) {
            const int k = kq + e;
            const int u = k >> 1;
            const int pu = u ^ ((u >> 5) & 3);
            rb[(pu << 2) + ((k & 1) << 1) + jl] = (&v.x)[e];
        }
    }
    // --- initial h (swizzled)
    for (int idx = tid; idx < BPC * 64; idx += 512) {
        const int b = idx >> 6; const int u = idx & 63;
        const float4 v = *(const float4*)(hx + ((size_t)(b0 + b) << 8) + (u << 2));
        const int s = u ^ ((u >> 4) & 3) ^ (b & 7);
        *(float4*)&s_rec[HOFF0 + (b << 8) + (s << 2)] = v;
    }

    int lmax = 0;
    #pragma unroll
    for (int i = 0; i < BPC; i++) lmax = max(lmax, g_len[b0 + i]);

    const int w    = tid >> 5;             // = jp (0..15)
    const int lane = tid & 31;
    const int bg   = lane & 7;
    const int ks   = lane >> 3;            // 0..3
    const int bsel = ks & 1;
    const int bloc = (bg << 1) + bsel;     // this lane's epilogue b
    const int Jg   = ((int)rank << 5) + (w << 1);
    const int bglob = b0 + bloc;
    const int blen  = g_len[bglob];
    const int ntrue = g_ntrue;

    const float2 bh_r = *(const float2*)(bhh + Jg);
    const float2 bh_z = *(const float2*)(bhh + 256 + Jg);
    const float2 bh_n = *(const float2*)(bhh + 512 + Jg);

    const float* wr = s_rec + WOFF + (w * 3 + 0) * WKF + (ks << 7); // +32ks units*4
    const float* wz = s_rec + WOFF + (w * 3 + 1) * WKF + (ks << 7);
    const float* wn = s_rec + WOFF + (w * 3 + 2) * WKF + (ks << 7);
    const int hb0 = ((bg << 1) << 8) + (ks << 6);       // b even row + 16ks units
    const int hb1 = (((bg << 1) + 1) << 8) + (ks << 6);
    const int hx0 = ks ^ ((bg << 1) & 7);               // iter XOR for b0
    const int hx1 = ks ^ (((bg << 1) + 1) & 7);         // for b1

    // precomputed DSMEM targets: (buffer, rank-quarter)
    const int myoff = h_off(bloc, Jg);                  // float offset of this lane's pair
    uint32_t rem[2][4];
    {
        const uint32_t a0 = sbase + ((HOFF0 + myoff) << 2);
        const uint32_t a1 = sbase + ((HOFF1 + myoff) << 2);
        #pragma unroll
        for (int r2 = 0; r2 < 4; r2++) {
            const int tr = ((ks >> 1) << 2) + r2;
            asm("mapa.shared::cluster.u32 %0, %1, %2;" : "=r"(rem[0][r2]) : "r"(a0), "r"(tr));
            asm("mapa.shared::cluster.u32 %0, %1, %2;" : "=r"(rem[1][r2]) : "r"(a1), "r"(tr));
        }
    }

    asm volatile("barrier.cluster.arrive.aligned;" ::: "memory");
    asm volatile("barrier.cluster.wait.aligned;"   ::: "memory");

    const float* gi_base = g_gi + (size_t)bglob * DG;

    for (int t = 0; t < lmax; t++) {
        const int cur = t & 1;
        const float* hc = s_rec + (cur ? HOFF1 : HOFF0);
        const int nflat = (t << 8) + bglob;
        const float* gp = gi_base + (size_t)t * (256 * DG);

        const float2 gi_r = __ldg((const float2*)(gp + Jg));
        const float2 gi_z = __ldg((const float2*)(gp + 256 + Jg));
        const float2 gi_n = __ldg((const float2*)(gp + 512 + Jg));
        int dest = -1;
        if ((t < blen) && (nflat < ntrue)) dest = __ldg(&g_order[nflat]);
        const float2 hold = *(const float2*)&hc[h_off(bloc, Jg)];

        u64 acc[3][2] = {{0ull,0ull},{0ull,0ull},{0ull,0ull}};
        #pragma unroll 4
        for (int it = 0; it < 16; it++) {
            const int e0 = ((it << 1) ^ ks) << 2;
            const int e1 = (((it << 1) + 1) ^ ks) << 2;
            const double2 r01 = make_double2(*(const double*)(wr + e0), *(const double*)(wr + e0 + 2));
            const double2 r23 = make_double2(*(const double*)(wr + e1), *(const double*)(wr + e1 + 2));
            const double2 z01 = make_double2(*(const double*)(wz + e0), *(const double*)(wz + e0 + 2));
            const double2 z23 = make_double2(*(const double*)(wz + e1), *(const double*)(wz + e1 + 2));
            const double2 n01 = make_double2(*(const double*)(wn + e0), *(const double*)(wn + e0 + 2));
            const double2 n23 = make_double2(*(const double*)(wn + e1), *(const double*)(wn + e1 + 2));
            const float4 h0 = *(const float4*)&hc[hb0 + ((it ^ hx0) << 2)];
            const float4 h1 = *(const float4*)&hc[hb1 + ((it ^ hx1) << 2)];

            const u64 p00 = pack2(h0.x, h0.x), p01 = pack2(h0.y, h0.y);
            const u64 p02 = pack2(h0.z, h0.z), p03 = pack2(h0.w, h0.w);
            const u64 p10 = pack2(h1.x, h1.x), p11 = pack2(h1.y, h1.y);
            const u64 p12 = pack2(h1.z, h1.z), p13 = pack2(h1.w, h1.w);

            fma2(acc[0][0], p00, __double_as_longlong(r01.x));
            fma2(acc[0][0], p01, __double_as_longlong(r01.y));
            fma2(acc[0][0], p02, __double_as_longlong(r23.x));
            fma2(acc[0][0], p03, __double_as_longlong(r23.y));
            fma2(acc[0][1], p10, __double_as_longlong(r01.x));
            fma2(acc[0][1], p11, __double_as_longlong(r01.y));
            fma2(acc[0][1], p12, __double_as_longlong(r23.x));
            fma2(acc[0][1], p13, __double_as_longlong(r23.y));
            fma2(acc[1][0], p00, __double_as_longlong(z01.x));
            fma2(acc[1][0], p01, __double_as_longlong(z01.y));
            fma2(acc[1][0], p02, __double_as_longlong(z23.x));
            fma2(acc[1][0], p03, __double_as_longlong(z23.y));
            fma2(acc[1][1], p10, __double_as_longlong(z01.x));
            fma2(acc[1][1], p11, __double_as_longlong(z01.y));
            fma2(acc[1][1], p12, __double_as_longlong(z23.x));
            fma2(acc[1][1], p13, __double_as_longlong(z23.y));
            fma2(acc[2][0], p00, __double_as_longlong(n01.x));
            fma2(acc[2][0], p01, __double_as_longlong(n01.y));
            fma2(acc[2][0], p02, __double_as_longlong(n23.x));
            fma2(acc[2][0], p03, __double_as_longlong(n23.y));
            fma2(acc[2][1], p10, __double_as_longlong(n01.x));
            fma2(acc[2][1], p11, __double_as_longlong(n01.y));
            fma2(acc[2][1], p12, __double_as_longlong(n23.x));
            fma2(acc[2][1], p13, __double_as_longlong(n23.y));
        }

        // reduce over ks (lane bits 3,4): all lanes end with full sums
        #pragma unroll
        for (int g = 0; g < 3; g++) {
            #pragma unroll
            for (int d = 0; d < 2; d++) {
                u64 v = acc[g][d];
                v = add2(v, __shfl_xor_sync(0xffffffffu, v, 8));
                v = add2(v, __shfl_xor_sync(0xffffffffu, v, 16));
                acc[g][d] = v;
            }
        }

        float ghr0, ghr1, ghz0, ghz1, ghn0, ghn1;
        unpack2(acc[0][bsel], ghr0, ghr1);
        unpack2(acc[1][bsel], ghz0, ghz1);
        unpack2(acc[2][bsel], ghn0, ghn1);

        float hn0, hn1;
        {
            const float r0 = 1.f / (1.f + __expf(-(gi_r.x + ghr0 + bh_r.x)));
            const float z0 = 1.f / (1.f + __expf(-(gi_z.x + ghz0 + bh_z.x)));
            const float n0 = tanhf(gi_n.x + r0 * (ghn0 + bh_n.x));
            hn0 = (1.f - z0) * n0 + z0 * hold.x;
            const float r1 = 1.f / (1.f + __expf(-(gi_r.y + ghr1 + bh_r.y)));
            const float z1 = 1.f / (1.f + __expf(-(gi_z.y + ghz1 + bh_z.y)));
            const float n1 = tanhf(gi_n.y + r1 * (ghn1 + bh_n.y));
            hn1 = (1.f - z1) * n1 + z1 * hold.y;
        }
        if (t >= blen) { hn0 = hold.x; hn1 = hold.y; }

        const u64 pk = pack2(hn0, hn1);
        const int nxt = cur ^ 1;
        #pragma unroll
        for (int r2 = 0; r2 < 4; r2++) {
            asm volatile("st.shared::cluster.b64 [%0], %1;"
                         :: "r"(nxt ? rem[1][r2] : rem[0][r2]), "l"(pk) : "memory");
        }

        if (ks < 2 && dest >= 0) {
            const size_t o = ((size_t)dest << 8) + Jg;
            if (o + 1 < oe) *(float2*)(out + o) = make_float2(hn0, hn1);
        }

        asm volatile("barrier.cluster.arrive.aligned;" ::: "memory");
        asm volatile("barrier.cluster.wait.aligned;"   ::: "memory");
    }

    // final hidden state
    if (ks < 2) {
        const float* hf = s_rec + ((lmax & 1) ? HOFF1 : HOFF0);
        const float2 hv = *(const float2*)&hf[h_off(bloc, Jg)];
        const size_t o = ((size_t)DP << 8) + ((size_t)bglob << 8) + Jg;
        if (o + 1 < oe) *(float2*)(out + o) = hv;
    }
}

// ---------------------------------------------------------------------------
__global__ void k_zero(float* __restrict__ out, const size_t n) {
    size_t i = (size_t)blockIdx.x * blockDim.x + threadIdx.x;
    const size_t stride = (size_t)gridDim.x * blockDim.x;
    for (; i < n; i += stride) out[i] = 0.f;
}

// ---------------------------------------------------------------------------
extern "C" void kernel_launch(void* const* d_in, const int* in_sizes, int n_in,
                              void* d_out, int out_size) {
    const float* x    = (const float*)d_in[0];
    const float* hx   = (const float*)d_in[1];
    const int*   mask = (const int*)  d_in[2];
    const float* Wih  = (const float*)d_in[3];
    const float* Whh  = (const float*)d_in[4];
    const float* bih  = (const float*)d_in[5];
    const float* bhh  = (const float*)d_in[6];
    float* out = (float*)d_out;
    const size_t oe = (size_t)out_size;

    static int s_attr_done = 0;
    if (!s_attr_done) {
        cudaFuncSetAttribute(k_rec, cudaFuncAttributeMaxDynamicSharedMemorySize,
                             SMEM_F * 4);
        s_attr_done = 1;
    }

    k_prep<<<1, 1024>>>(mask);
    k_zero<<<2048, 256>>>(out, oe);
    k_gi<<<dim3(12, 2048), 256>>>(x, Wih, bih);
    k_rec<<<128, 512, SMEM_F * 4>>>(Whh, bhh, hx, out, oe);
}